// round 3
// baseline (speedup 1.0000x reference)
#include <cuda_runtime.h>
#include <cuda_bf16.h>

#define NN 50000
#define NE 600000
#define HID 128

// ---------------- scratch (static device globals; no allocations) ------------
__device__ int   g_is64;
__device__ int   g_deg[NN];
__device__ int   g_rowptr[NN];
__device__ int   g_cursor[NN];
__device__ float g_inv[NN];
__device__ int   g_col[NE];
__device__ int   g_bsums[64];
__device__ float g_mean[(size_t)NN * HID];
__device__ float g_h1[(size_t)NN * HID];
__device__ float g_h2[(size_t)NN * HID];

// ---------------- dtype probe: is edge_index int64 or int32? -----------------
// First 64 src entries occupy <= 512 bytes under either interpretation (buffer
// is >= 4.8 MB), so both reads are in bounds. int32 data misread as int64
// packs two indices per word -> value >= 2^32 -> out of range.
__global__ void k_detect(const void* __restrict__ ei_raw) {
    if (threadIdx.x == 0 && blockIdx.x == 0) {
        const long long* p = (const long long*)ei_raw;
        int ok = 1;
        for (int e = 0; e < 64; e++) {
            long long v = p[e];
            if (v < 0 || v >= NN) { ok = 0; break; }
        }
        g_is64 = ok;
    }
}

__device__ __forceinline__ int edge_val(const void* ei_raw, int idx) {
    if (g_is64) return (int)((const long long*)ei_raw)[idx];
    return ((const int*)ei_raw)[idx];
}

// ---------------- CSR build --------------------------------------------------
__global__ void k_zero_deg() {
    int i = blockIdx.x * blockDim.x + threadIdx.x;
    if (i < NN) g_deg[i] = 0;
}

__global__ void k_count(const void* __restrict__ ei) {
    int e = blockIdx.x * blockDim.x + threadIdx.x;
    if (e < NE) {
        int d = edge_val(ei, NE + e);   // dst
        if ((unsigned)d < NN) atomicAdd(&g_deg[d], 1);
    }
}

// per-block inclusive scan of 1024 degrees -> local exclusive + block sums
__global__ void k_scan1() {
    __shared__ int sh[1024];
    int i = blockIdx.x * 1024 + threadIdx.x;
    int v = (i < NN) ? g_deg[i] : 0;
    sh[threadIdx.x] = v;
    __syncthreads();
#pragma unroll
    for (int o = 1; o < 1024; o <<= 1) {
        int t = (threadIdx.x >= o) ? sh[threadIdx.x - o] : 0;
        __syncthreads();
        sh[threadIdx.x] += t;
        __syncthreads();
    }
    if (i < NN) g_rowptr[i] = sh[threadIdx.x] - v;   // local exclusive
    if (threadIdx.x == 1023) g_bsums[blockIdx.x] = sh[1023];
}

__global__ void k_scan2(int nb) {
    if (blockIdx.x == 0 && threadIdx.x == 0) {
        int acc = 0;
        for (int b = 0; b < nb; b++) { int t = g_bsums[b]; g_bsums[b] = acc; acc += t; }
    }
}

__global__ void k_scan3() {
    int i = blockIdx.x * blockDim.x + threadIdx.x;
    if (i < NN) {
        int rp = g_rowptr[i] + g_bsums[i >> 10];
        g_rowptr[i] = rp;
        g_cursor[i] = rp;
        int d = g_deg[i];
        g_inv[i] = 1.0f / (float)(d > 0 ? d : 1);
    }
}

__global__ void k_fill(const void* __restrict__ ei) {
    int e = blockIdx.x * blockDim.x + threadIdx.x;
    if (e < NE) {
        int s = edge_val(ei, e);
        int d = edge_val(ei, NE + e);
        if ((unsigned)s < NN && (unsigned)d < NN) {
            int pos = atomicAdd(&g_cursor[d], 1);
            if ((unsigned)pos < NE) g_col[pos] = s;
        }
    }
}

// ---------------- aggregation: block per node, 128 threads = 1 feature row ---
// src_sel: 0 = external x pointer, 1 = g_h1, 2 = g_h2.  Output: g_mean.
__global__ void __launch_bounds__(128) k_agg(const float* __restrict__ x_ext,
                                             int src_sel) {
    const float* in = (src_sel == 0) ? x_ext : (src_sel == 1 ? g_h1 : g_h2);
    int i = blockIdx.x;
    int t = threadIdx.x;
    int s = g_rowptr[i];
    int d = g_deg[i];
    float acc = 0.f;
    int k = 0;
    for (; k + 4 <= d; k += 4) {
        int j0 = g_col[s + k + 0];
        int j1 = g_col[s + k + 1];
        int j2 = g_col[s + k + 2];
        int j3 = g_col[s + k + 3];
        float v0 = __ldg(in + (size_t)j0 * HID + t);
        float v1 = __ldg(in + (size_t)j1 * HID + t);
        float v2 = __ldg(in + (size_t)j2 * HID + t);
        float v3 = __ldg(in + (size_t)j3 * HID + t);
        acc += (v0 + v1) + (v2 + v3);
    }
    for (; k < d; k++) {
        int j = g_col[s + k];
        acc += __ldg(in + (size_t)j * HID + t);
    }
    g_mean[(size_t)i * HID + t] = acc * g_inv[i];
}

// ---------------- fused SGEMM: out = mean@Wl^T + in@Wr^T + b (opt. ReLU) -----
// Block = 128 rows x 128 cols, 256 threads, 8x8 register tile per thread.
// Virtual K = 256: k<128 uses (g_mean, Wl), k>=128 uses (Ain, Wr).
// src_sel: 0 = x_ext, 1 = g_h1, 2 = g_h2.  dst_sel: 1 = g_h1, 2 = g_h2, 3 = out_ext.
__global__ void __launch_bounds__(256, 2) k_gemm(
    const float* __restrict__ x_ext,
    const float* __restrict__ Wl,    const float* __restrict__ Wr,
    const float* __restrict__ bias,  float* __restrict__ out_ext,
    int src_sel, int dst_sel, int relu)
{
    const float* Ain = (src_sel == 0) ? x_ext : (src_sel == 1 ? g_h1 : g_h2);
    float* out = (dst_sel == 1) ? g_h1 : (dst_sel == 2 ? g_h2 : out_ext);

    __shared__ float As[8][128];   // [kk][row]
    __shared__ float Bs[8][128];   // [kk][n]
    int tid = threadIdx.x;
    int tx = tid & 15;             // col group
    int ty = tid >> 4;             // row group
    int row0 = blockIdx.x * 128;
    int lr = tid >> 1;             // load row (A) / load n (W): 0..127
    int lc = (tid & 1) * 4;        // k sub-offset: 0 or 4

    float acc[8][8];
#pragma unroll
    for (int i = 0; i < 8; i++)
#pragma unroll
        for (int j = 0; j < 8; j++) acc[i][j] = 0.f;

    for (int kb = 0; kb < 256; kb += 8) {
        const float* A = (kb < 128) ? g_mean : Ain;
        const float* W = (kb < 128) ? Wl : Wr;
        int kloc = kb & 127;

        float4 av = make_float4(0.f, 0.f, 0.f, 0.f);
        int grow = row0 + lr;
        if (grow < NN)
            av = *(const float4*)(A + (size_t)grow * HID + kloc + lc);
        float4 bv = *(const float4*)(W + (size_t)lr * HID + kloc + lc);

        __syncthreads();           // protect previous tile reads
        As[lc + 0][lr] = av.x; As[lc + 1][lr] = av.y;
        As[lc + 2][lr] = av.z; As[lc + 3][lr] = av.w;
        Bs[lc + 0][lr] = bv.x; Bs[lc + 1][lr] = bv.y;
        Bs[lc + 2][lr] = bv.z; Bs[lc + 3][lr] = bv.w;
        __syncthreads();

#pragma unroll
        for (int kk = 0; kk < 8; kk++) {
            float4 a0 = *(const float4*)&As[kk][ty * 4];
            float4 a1 = *(const float4*)&As[kk][64 + ty * 4];
            float4 b0 = *(const float4*)&Bs[kk][tx * 4];
            float4 b1 = *(const float4*)&Bs[kk][64 + tx * 4];
            float a[8] = {a0.x, a0.y, a0.z, a0.w, a1.x, a1.y, a1.z, a1.w};
            float b[8] = {b0.x, b0.y, b0.z, b0.w, b1.x, b1.y, b1.z, b1.w};
#pragma unroll
            for (int i = 0; i < 8; i++)
#pragma unroll
                for (int j = 0; j < 8; j++)
                    acc[i][j] += a[i] * b[j];
        }
    }

    // epilogue: bias + optional relu, float4 stores
    float bc0[4], bc1[4];
#pragma unroll
    for (int j = 0; j < 4; j++) {
        bc0[j] = __ldg(bias + tx * 4 + j);
        bc1[j] = __ldg(bias + 64 + tx * 4 + j);
    }
#pragma unroll
    for (int i = 0; i < 8; i++) {
        int r = (i < 4) ? (ty * 4 + i) : (64 + ty * 4 + (i - 4));
        int grow = row0 + r;
        if (grow < NN) {
            float4 o0, o1;
            o0.x = acc[i][0] + bc0[0]; o0.y = acc[i][1] + bc0[1];
            o0.z = acc[i][2] + bc0[2]; o0.w = acc[i][3] + bc0[3];
            o1.x = acc[i][4] + bc1[0]; o1.y = acc[i][5] + bc1[1];
            o1.z = acc[i][6] + bc1[2]; o1.w = acc[i][7] + bc1[3];
            if (relu) {
                o0.x = fmaxf(o0.x, 0.f); o0.y = fmaxf(o0.y, 0.f);
                o0.z = fmaxf(o0.z, 0.f); o0.w = fmaxf(o0.w, 0.f);
                o1.x = fmaxf(o1.x, 0.f); o1.y = fmaxf(o1.y, 0.f);
                o1.z = fmaxf(o1.z, 0.f); o1.w = fmaxf(o1.w, 0.f);
            }
            *(float4*)(out + (size_t)grow * HID + tx * 4) = o0;
            *(float4*)(out + (size_t)grow * HID + 64 + tx * 4) = o1;
        }
    }
}

// ---------------- launch -----------------------------------------------------
extern "C" void kernel_launch(void* const* d_in, const int* in_sizes, int n_in,
                              void* d_out, int out_size) {
    const float* x   = (const float*)d_in[0];
    const void*  ei  = d_in[1];                 // int32 or int64, probed on device
    const float* Wl1 = (const float*)d_in[2];
    const float* Wr1 = (const float*)d_in[3];
    const float* b1  = (const float*)d_in[4];
    const float* Wl2 = (const float*)d_in[5];
    const float* Wr2 = (const float*)d_in[6];
    const float* b2  = (const float*)d_in[7];
    const float* Wl3 = (const float*)d_in[8];
    const float* Wr3 = (const float*)d_in[9];
    const float* b3  = (const float*)d_in[10];
    float* out = (float*)d_out;

    // CSR build (reused by all 3 layers)
    k_detect<<<1, 32>>>(ei);
    k_zero_deg<<<(NN + 255) / 256, 256>>>();
    k_count<<<(NE + 255) / 256, 256>>>(ei);
    int nb = (NN + 1023) / 1024;
    k_scan1<<<nb, 1024>>>();
    k_scan2<<<1, 32>>>(nb);
    k_scan3<<<(NN + 255) / 256, 256>>>();
    k_fill<<<(NE + 255) / 256, 256>>>(ei);

    int gblocks = (NN + 127) / 128;

    // layer 1 (ReLU): agg(x) -> mean; gemm(mean, x) -> h1
    k_agg<<<NN, 128>>>(x, 0);
    k_gemm<<<gblocks, 256>>>(x, Wl1, Wr1, b1, out, 0, 1, 1);
    // layer 2: agg(h1) -> mean; gemm(mean, h1) -> h2
    k_agg<<<NN, 128>>>(x, 1);
    k_gemm<<<gblocks, 256>>>(x, Wl2, Wr2, b2, out, 1, 2, 0);
    // layer 3: agg(h2) -> mean; gemm(mean, h2) -> d_out
    k_agg<<<NN, 128>>>(x, 2);
    k_gemm<<<gblocks, 256>>>(x, Wl3, Wr3, b3, out, 2, 3, 0);
}

// round 6
// speedup vs baseline: 1.3536x; 1.3536x over previous
#include <cuda_runtime.h>
#include <cuda_bf16.h>
#include <cstdint>

#define NN 50000
#define NE 600000
#define HID 128
#define TILE_M 128
#define GBLK ((NN + TILE_M - 1) / TILE_M)

// ---------------- scratch (static device globals; no allocations) ------------
__device__ int   g_is64;
__device__ int   g_deg[NN];
__device__ int   g_rowptr[NN];
__device__ int   g_cursor[NN];
__device__ float g_inv[NN];
__device__ int   g_col[NE];
__device__ int   g_bsums[64];
__device__ float g_mean[(size_t)NN * HID];
__device__ float g_h1[(size_t)NN * HID];
__device__ float g_h2[(size_t)NN * HID];

// ---------------- helpers ----------------------------------------------------
__device__ __forceinline__ uint32_t smem_u32(const void* p) {
    uint32_t a;
    asm("{ .reg .u64 t; cvta.to.shared.u64 t, %1; cvt.u32.u64 %0, t; }"
        : "=r"(a) : "l"(p));
    return a;
}

#define SWZ(o) ((o) ^ (((o) >> 3) & 0x70))

__device__ __forceinline__ void ldsm4(uint32_t* r, uint32_t addr) {
    asm volatile("ldmatrix.sync.aligned.m8n8.x4.shared.b16 {%0,%1,%2,%3}, [%4];"
                 : "=r"(r[0]), "=r"(r[1]), "=r"(r[2]), "=r"(r[3]) : "r"(addr));
}

__device__ __forceinline__ void mma_bf16(float* c, const uint32_t* a,
                                         const uint32_t* b) {
    asm volatile(
        "mma.sync.aligned.m16n8k16.row.col.f32.bf16.bf16.f32 "
        "{%0,%1,%2,%3}, {%4,%5,%6,%7}, {%8,%9}, {%0,%1,%2,%3};"
        : "+f"(c[0]), "+f"(c[1]), "+f"(c[2]), "+f"(c[3])
        : "r"(a[0]), "r"(a[1]), "r"(a[2]), "r"(a[3]), "r"(b[0]), "r"(b[1]));
}

// ---------------- dtype probe ------------------------------------------------
__global__ void k_detect(const void* __restrict__ ei_raw) {
    if (threadIdx.x == 0 && blockIdx.x == 0) {
        const long long* p = (const long long*)ei_raw;
        int ok = 1;
        for (int e = 0; e < 64; e++) {
            long long v = p[e];
            if (v < 0 || v >= NN) { ok = 0; break; }
        }
        g_is64 = ok;
    }
}

__device__ __forceinline__ int edge_val(const void* ei_raw, int idx) {
    if (g_is64) return (int)((const long long*)ei_raw)[idx];
    return ((const int*)ei_raw)[idx];
}

// ---------------- CSR build --------------------------------------------------
__global__ void k_zero_deg() {
    int i = blockIdx.x * blockDim.x + threadIdx.x;
    if (i < NN) g_deg[i] = 0;
}

__global__ void k_count(const void* __restrict__ ei) {
    int e = blockIdx.x * blockDim.x + threadIdx.x;
    if (e < NE) {
        int d = edge_val(ei, NE + e);
        if ((unsigned)d < NN) atomicAdd(&g_deg[d], 1);
    }
}

__global__ void k_scan1() {
    __shared__ int sh[1024];
    int i = blockIdx.x * 1024 + threadIdx.x;
    int v = (i < NN) ? g_deg[i] : 0;
    sh[threadIdx.x] = v;
    __syncthreads();
#pragma unroll
    for (int o = 1; o < 1024; o <<= 1) {
        int t = (threadIdx.x >= o) ? sh[threadIdx.x - o] : 0;
        __syncthreads();
        sh[threadIdx.x] += t;
        __syncthreads();
    }
    if (i < NN) g_rowptr[i] = sh[threadIdx.x] - v;
    if (threadIdx.x == 1023) g_bsums[blockIdx.x] = sh[1023];
}

__global__ void k_scan2(int nb) {
    if (blockIdx.x == 0 && threadIdx.x == 0) {
        int acc = 0;
        for (int b = 0; b < nb; b++) { int t = g_bsums[b]; g_bsums[b] = acc; acc += t; }
    }
}

__global__ void k_scan3() {
    int i = blockIdx.x * blockDim.x + threadIdx.x;
    if (i < NN) {
        int rp = g_rowptr[i] + g_bsums[i >> 10];
        g_rowptr[i] = rp;
        g_cursor[i] = rp;
        int d = g_deg[i];
        g_inv[i] = 1.0f / (float)(d > 0 ? d : 1);
    }
}

__global__ void k_fill(const void* __restrict__ ei) {
    int e = blockIdx.x * blockDim.x + threadIdx.x;
    if (e < NE) {
        int s = edge_val(ei, e);
        int d = edge_val(ei, NE + e);
        if ((unsigned)s < NN && (unsigned)d < NN) {
            int pos = atomicAdd(&g_cursor[d], 1);
            if ((unsigned)pos < NE) g_col[pos] = s;
        }
    }
}

// ---------------- aggregation: block per node, 128 threads = 1 feature row ---
__global__ void __launch_bounds__(128) k_agg(const float* __restrict__ x_ext,
                                             int src_sel) {
    const float* in = (src_sel == 0) ? x_ext : (src_sel == 1 ? g_h1 : g_h2);
    int i = blockIdx.x;
    int t = threadIdx.x;
    int s = g_rowptr[i];
    int d = g_deg[i];
    float acc = 0.f;
    int k = 0;
    for (; k + 4 <= d; k += 4) {
        int j0 = g_col[s + k + 0];
        int j1 = g_col[s + k + 1];
        int j2 = g_col[s + k + 2];
        int j3 = g_col[s + k + 3];
        float v0 = __ldg(in + (size_t)j0 * HID + t);
        float v1 = __ldg(in + (size_t)j1 * HID + t);
        float v2 = __ldg(in + (size_t)j2 * HID + t);
        float v3 = __ldg(in + (size_t)j3 * HID + t);
        acc += (v0 + v1) + (v2 + v3);
    }
    for (; k < d; k++) {
        int j = g_col[s + k];
        acc += __ldg(in + (size_t)j * HID + t);
    }
    g_mean[(size_t)i * HID + t] = acc * g_inv[i];
}

// ---------------- mma.sync GEMM ----------------------------------------------
// out = mean @ Wl^T + h @ Wr^T + b (opt ReLU) via compensated bf16 split:
// C += Ahi*Bhi + Ahi*Blo + Alo*Bhi, fp32 register accumulators.
// CTA: 128x128 tile, 256 thr (8 warps, 4m x 2n), K=256 in 4 chunks of 64.
// smem per chunk: A hi/lo + W hi/lo, each 128 rows x 128B (SW128 swizzled).
#define SM_AHI  0
#define SM_ALO  16384
#define SM_WHI  32768
#define SM_WLO  49152
#define SM_TOTAL 65536

__device__ __forceinline__ uint32_t pack_bf2(__nv_bfloat16 a, __nv_bfloat16 b) {
    __nv_bfloat162 t = __halves2bfloat162(a, b);
    return *(uint32_t*)&t;
}

__device__ __forceinline__ void cvt_store_row4(char* hi_base, char* lo_base,
                                               int row, int g, float4 v) {
    __nv_bfloat16 h0 = __float2bfloat16_rn(v.x);
    __nv_bfloat16 h1 = __float2bfloat16_rn(v.y);
    __nv_bfloat16 h2 = __float2bfloat16_rn(v.z);
    __nv_bfloat16 h3 = __float2bfloat16_rn(v.w);
    __nv_bfloat16 l0 = __float2bfloat16_rn(v.x - __bfloat162float(h0));
    __nv_bfloat16 l1 = __float2bfloat16_rn(v.y - __bfloat162float(h1));
    __nv_bfloat16 l2 = __float2bfloat16_rn(v.z - __bfloat162float(h2));
    __nv_bfloat16 l3 = __float2bfloat16_rn(v.w - __bfloat162float(h3));
    uint32_t off = SWZ((uint32_t)(row * 128 + g * 8));
    *(uint2*)(hi_base + off) = make_uint2(pack_bf2(h0, h1), pack_bf2(h2, h3));
    *(uint2*)(lo_base + off) = make_uint2(pack_bf2(l0, l1), pack_bf2(l2, l3));
}

__global__ void __launch_bounds__(256, 2) k_mma(
    const float* __restrict__ x_ext,
    const float* __restrict__ Wl, const float* __restrict__ Wr,
    const float* __restrict__ bias, float* __restrict__ out_ext,
    int src_sel, int dst_sel, int relu)
{
    extern __shared__ char smem[];
    const float* Ain = (src_sel == 0) ? x_ext : (src_sel == 1 ? g_h1 : g_h2);
    float* out = (dst_sel == 1) ? g_h1 : (dst_sel == 2 ? g_h2 : out_ext);

    uint32_t sb = smem_u32(smem);
    int tid = threadIdx.x;
    int lane = tid & 31, warp = tid >> 5;
    int wm = warp & 3, wn = warp >> 2;      // 4m x 2n warp grid
    int row0 = blockIdx.x * TILE_M;

    float acc[2][8][4];
#pragma unroll
    for (int mt = 0; mt < 2; mt++)
#pragma unroll
        for (int nt = 0; nt < 8; nt++)
#pragma unroll
            for (int q = 0; q < 4; q++) acc[mt][nt][q] = 0.f;

    // lane-derived ldmatrix address components
    int l15 = lane & 15, lhi = lane >> 4;             // A: row sel, k-half
    int bn = ((lane >> 4) << 3) + (lane & 7);         // B: n row within 16
    int bk = ((lane >> 3) & 1) * 16;                  // B: k-half byte off

    int frow = tid >> 1;          // fill row (0..127)
    int fhalf = tid & 1;          // fill k-half of chunk (0..1)

    for (int kc = 0; kc < 4; kc++) {
        const float* Asrc = (kc < 2) ? g_mean : Ain;
        const float* Wsrc = (kc < 2) ? Wl : Wr;
        int koff = (kc & 1) * 64;

        // ---- fill smem chunk (A rows / W rows), fp32 -> bf16 hi/lo ----
        {
            int grow = row0 + frow;
            bool ok = grow < NN;
            const float* ap = Asrc + (size_t)grow * HID + koff + fhalf * 32;
            const float* wp = Wsrc + (size_t)frow * HID + koff + fhalf * 32;
#pragma unroll
            for (int g = 0; g < 8; g++) {
                float4 va = ok ? *(const float4*)(ap + g * 4)
                               : make_float4(0.f, 0.f, 0.f, 0.f);
                cvt_store_row4(smem + SM_AHI, smem + SM_ALO, frow,
                               fhalf * 8 + g, va);
                float4 vw = *(const float4*)(wp + g * 4);
                cvt_store_row4(smem + SM_WHI, smem + SM_WLO, frow,
                               fhalf * 8 + g, vw);
            }
        }
        __syncthreads();

        // ---- 4 x k16 steps of mma ----
#pragma unroll
        for (int ks = 0; ks < 4; ks++) {
            int kb2 = ks * 32;    // byte offset of this k16 step
            uint32_t a_hi[2][4], a_lo[2][4];
#pragma unroll
            for (int mt = 0; mt < 2; mt++) {
                uint32_t off = (uint32_t)((wm * 32 + mt * 16 + l15) * 128 +
                                          kb2 + lhi * 16);
                uint32_t so = SWZ(off);
                ldsm4(a_hi[mt], sb + SM_AHI + so);
                ldsm4(a_lo[mt], sb + SM_ALO + so);
            }
#pragma unroll
            for (int g = 0; g < 4; g++) {
                uint32_t offb = (uint32_t)((wn * 64 + g * 16 + bn) * 128 +
                                           kb2 + bk);
                uint32_t so = SWZ(offb);
                uint32_t bh[4], bl[4];
                ldsm4(bh, sb + SM_WHI + so);
                ldsm4(bl, sb + SM_WLO + so);
#pragma unroll
                for (int mt = 0; mt < 2; mt++)
#pragma unroll
                    for (int sub = 0; sub < 2; sub++) {
                        float* c = acc[mt][g * 2 + sub];
                        mma_bf16(c, a_hi[mt], bh + sub * 2);
                        mma_bf16(c, a_hi[mt], bl + sub * 2);
                        mma_bf16(c, a_lo[mt], bh + sub * 2);
                    }
            }
        }
        __syncthreads();
    }

    // ---- epilogue: bias + opt relu, float2 stores ----
#pragma unroll
    for (int nt = 0; nt < 8; nt++) {
        int col = wn * 64 + nt * 8 + (lane & 3) * 2;
        float bx = __ldg(bias + col);
        float by = __ldg(bias + col + 1);
#pragma unroll
        for (int mt = 0; mt < 2; mt++) {
            int r0 = row0 + wm * 32 + mt * 16 + (lane >> 2);
            float* c = acc[mt][nt];
            float2 o0 = make_float2(c[0] + bx, c[1] + by);
            float2 o1 = make_float2(c[2] + bx, c[3] + by);
            if (relu) {
                o0.x = fmaxf(o0.x, 0.f); o0.y = fmaxf(o0.y, 0.f);
                o1.x = fmaxf(o1.x, 0.f); o1.y = fmaxf(o1.y, 0.f);
            }
            if (r0 < NN)     *(float2*)(out + (size_t)r0 * HID + col) = o0;
            if (r0 + 8 < NN) *(float2*)(out + (size_t)(r0 + 8) * HID + col) = o1;
        }
    }
}

// ---------------- launch -----------------------------------------------------
extern "C" void kernel_launch(void* const* d_in, const int* in_sizes, int n_in,
                              void* d_out, int out_size) {
    const float* x   = (const float*)d_in[0];
    const void*  ei  = d_in[1];
    const float* Wl1 = (const float*)d_in[2];
    const float* Wr1 = (const float*)d_in[3];
    const float* b1  = (const float*)d_in[4];
    const float* Wl2 = (const float*)d_in[5];
    const float* Wr2 = (const float*)d_in[6];
    const float* b2  = (const float*)d_in[7];
    const float* Wl3 = (const float*)d_in[8];
    const float* Wr3 = (const float*)d_in[9];
    const float* b3  = (const float*)d_in[10];
    float* out = (float*)d_out;

    cudaFuncSetAttribute(k_mma, cudaFuncAttributeMaxDynamicSharedMemorySize,
                         SM_TOTAL);

    // CSR build (reused by all 3 layers)
    k_detect<<<1, 32>>>(ei);
    k_zero_deg<<<(NN + 255) / 256, 256>>>();
    k_count<<<(NE + 255) / 256, 256>>>(ei);
    int nb = (NN + 1023) / 1024;
    k_scan1<<<nb, 1024>>>();
    k_scan2<<<1, 32>>>(nb);
    k_scan3<<<(NN + 255) / 256, 256>>>();
    k_fill<<<(NE + 255) / 256, 256>>>(ei);

    // layer 1 (ReLU)
    k_agg<<<NN, 128>>>(x, 0);
    k_mma<<<GBLK, 256, SM_TOTAL>>>(x, Wl1, Wr1, b1, out, 0, 1, 1);
    // layer 2
    k_agg<<<NN, 128>>>(x, 1);
    k_mma<<<GBLK, 256, SM_TOTAL>>>(x, Wl2, Wr2, b2, out, 1, 2, 0);
    // layer 3
    k_agg<<<NN, 128>>>(x, 2);
    k_mma<<<GBLK, 256, SM_TOTAL>>>(x, Wl3, Wr3, b3, out, 2, 3, 0);
}

// round 8
// speedup vs baseline: 1.6181x; 1.1954x over previous
#include <cuda_runtime.h>
#include <cuda_bf16.h>
#include <cstdint>

#define NN 50000
#define NE 600000
#define HID 128
#define TILE_M 128
#define GBLK ((NN + TILE_M - 1) / TILE_M)

typedef __nv_bfloat16 bf16;

// ---------------- scratch (static device globals; no allocations) ------------
__device__ int   g_is64;
__device__ int   g_deg[NN];
__device__ int   g_rowptr[NN];
__device__ int   g_cursor[NN];
__device__ float g_inv[NN];
__device__ int   g_col[NE];
__device__ int   g_bsums[64];
__device__ float g_h1[(size_t)NN * HID];
__device__ float g_h2[(size_t)NN * HID];
// bf16 hi/lo split operand buffers
__device__ bf16  g_mhi[(size_t)NN * HID], g_mlo[(size_t)NN * HID];
__device__ bf16  g_xhi[(size_t)NN * HID], g_xlo[(size_t)NN * HID];
__device__ bf16  g_h1hi[(size_t)NN * HID], g_h1lo[(size_t)NN * HID];
__device__ bf16  g_h2hi[(size_t)NN * HID], g_h2lo[(size_t)NN * HID];
__device__ bf16  g_whi[6 * HID * HID], g_wlo[6 * HID * HID];

// ---------------- helpers ----------------------------------------------------
__device__ __forceinline__ uint32_t smem_u32(const void* p) {
    uint32_t a;
    asm("{ .reg .u64 t; cvta.to.shared.u64 t, %1; cvt.u32.u64 %0, t; }"
        : "=r"(a) : "l"(p));
    return a;
}

#define SWZ(o) ((o) ^ (((o) >> 3) & 0x70))

__device__ __forceinline__ void ldsm4(uint32_t* r, uint32_t addr) {
    asm volatile("ldmatrix.sync.aligned.m8n8.x4.shared.b16 {%0,%1,%2,%3}, [%4];"
                 : "=r"(r[0]), "=r"(r[1]), "=r"(r[2]), "=r"(r[3]) : "r"(addr));
}

__device__ __forceinline__ void mma_bf16(float* c, const uint32_t* a,
                                         const uint32_t* b) {
    asm volatile(
        "mma.sync.aligned.m16n8k16.row.col.f32.bf16.bf16.f32 "
        "{%0,%1,%2,%3}, {%4,%5,%6,%7}, {%8,%9}, {%0,%1,%2,%3};"
        : "+f"(c[0]), "+f"(c[1]), "+f"(c[2]), "+f"(c[3])
        : "r"(a[0]), "r"(a[1]), "r"(a[2]), "r"(a[3]), "r"(b[0]), "r"(b[1]));
}

__device__ __forceinline__ void split_bf(float v, bf16& h, bf16& l) {
    h = __float2bfloat16_rn(v);
    l = __float2bfloat16_rn(v - __bfloat162float(h));
}

__device__ __forceinline__ uint32_t pack_bf2(bf16 a, bf16 b) {
    __nv_bfloat162 t = __halves2bfloat162(a, b);
    return *(uint32_t*)&t;
}

// ---------------- dtype probe ------------------------------------------------
__global__ void k_detect(const void* __restrict__ ei_raw) {
    if (threadIdx.x == 0 && blockIdx.x == 0) {
        const long long* p = (const long long*)ei_raw;
        int ok = 1;
        for (int e = 0; e < 64; e++) {
            long long v = p[e];
            if (v < 0 || v >= NN) { ok = 0; break; }
        }
        g_is64 = ok;
    }
}

__device__ __forceinline__ int edge_val(const void* ei_raw, int idx) {
    if (g_is64) return (int)((const long long*)ei_raw)[idx];
    return ((const int*)ei_raw)[idx];
}

// ---------------- CSR build --------------------------------------------------
__global__ void k_zero_deg() {
    int i = blockIdx.x * blockDim.x + threadIdx.x;
    if (i < NN) g_deg[i] = 0;
}

__global__ void k_count(const void* __restrict__ ei) {
    int e = blockIdx.x * blockDim.x + threadIdx.x;
    if (e < NE) {
        int d = edge_val(ei, NE + e);
        if ((unsigned)d < NN) atomicAdd(&g_deg[d], 1);
    }
}

__global__ void k_scan1() {
    __shared__ int wsum[32];
    int i = blockIdx.x * 1024 + threadIdx.x;
    int lane = threadIdx.x & 31, w = threadIdx.x >> 5;
    int v = (i < NN) ? g_deg[i] : 0;
    int s = v;
#pragma unroll
    for (int o = 1; o < 32; o <<= 1) {
        int t = __shfl_up_sync(0xffffffffu, s, o);
        if (lane >= o) s += t;
    }
    if (lane == 31) wsum[w] = s;
    __syncthreads();
    if (w == 0) {
        int ws = wsum[lane];
#pragma unroll
        for (int o = 1; o < 32; o <<= 1) {
            int t = __shfl_up_sync(0xffffffffu, ws, o);
            if (lane >= o) ws += t;
        }
        wsum[lane] = ws;
    }
    __syncthreads();
    int incl = s + (w > 0 ? wsum[w - 1] : 0);
    if (i < NN) g_rowptr[i] = incl - v;
    if (threadIdx.x == 1023) g_bsums[blockIdx.x] = incl;
}

__global__ void k_scan2(int nb) {
    if (blockIdx.x == 0 && threadIdx.x == 0) {
        int acc = 0;
        for (int b = 0; b < nb; b++) { int t = g_bsums[b]; g_bsums[b] = acc; acc += t; }
    }
}

__global__ void k_scan3() {
    int i = blockIdx.x * blockDim.x + threadIdx.x;
    if (i < NN) {
        int rp = g_rowptr[i] + g_bsums[i >> 10];
        g_rowptr[i] = rp;
        g_cursor[i] = rp;
        int d = g_deg[i];
        g_inv[i] = 1.0f / (float)(d > 0 ? d : 1);
    }
}

__global__ void k_fill(const void* __restrict__ ei) {
    int e = blockIdx.x * blockDim.x + threadIdx.x;
    if (e < NE) {
        int s = edge_val(ei, e);
        int d = edge_val(ei, NE + e);
        if ((unsigned)s < NN && (unsigned)d < NN) {
            int pos = atomicAdd(&g_cursor[d], 1);
            if ((unsigned)pos < NE) g_col[pos] = s;
        }
    }
}

// ---------------- pre-convert: weights + x to bf16 hi/lo ---------------------
__global__ void k_wconv(const float* __restrict__ w0, const float* __restrict__ w1,
                        const float* __restrict__ w2, const float* __restrict__ w3,
                        const float* __restrict__ w4, const float* __restrict__ w5) {
    int idx = blockIdx.x * blockDim.x + threadIdx.x;
    if (idx >= 6 * HID * HID) return;
    int m = idx >> 14, off = idx & 16383;
    const float* w = (m == 0) ? w0 : (m == 1) ? w1 : (m == 2) ? w2
                   : (m == 3) ? w3 : (m == 4) ? w4 : w5;
    bf16 h, l;
    split_bf(w[off], h, l);
    g_whi[idx] = h; g_wlo[idx] = l;
}

__global__ void k_xconv(const float* __restrict__ x) {
    int idx = blockIdx.x * blockDim.x + threadIdx.x;   // per 4 elements
    if ((size_t)idx * 4 >= (size_t)NN * HID) return;
    float4 v = *(const float4*)(x + (size_t)idx * 4);
    bf16 h0, l0, h1, l1, h2, l2, h3, l3;
    split_bf(v.x, h0, l0); split_bf(v.y, h1, l1);
    split_bf(v.z, h2, l2); split_bf(v.w, h3, l3);
    *(uint2*)(g_xhi + (size_t)idx * 4) = make_uint2(pack_bf2(h0, h1), pack_bf2(h2, h3));
    *(uint2*)(g_xlo + (size_t)idx * 4) = make_uint2(pack_bf2(l0, l1), pack_bf2(l2, l3));
}

// ---------------- aggregation: warp per node, lane = float4 of features ------
// Writes mean directly as bf16 hi/lo (no fp32 mean buffer).
__global__ void __launch_bounds__(256) k_agg(const float* __restrict__ x_ext,
                                             int src_sel) {
    const float* in = (src_sel == 0) ? x_ext : (src_sel == 1 ? g_h1 : g_h2);
    int node = blockIdx.x * 8 + (threadIdx.x >> 5);
    int lane = threadIdx.x & 31;
    if (node >= NN) return;
    int s = g_rowptr[node];
    int d = g_deg[node];
    float4 acc = make_float4(0.f, 0.f, 0.f, 0.f);
    int k = 0;
    for (; k + 4 <= d; k += 4) {
        int j0 = g_col[s + k + 0];
        int j1 = g_col[s + k + 1];
        int j2 = g_col[s + k + 2];
        int j3 = g_col[s + k + 3];
        float4 v0 = __ldg((const float4*)(in + (size_t)j0 * HID) + lane);
        float4 v1 = __ldg((const float4*)(in + (size_t)j1 * HID) + lane);
        float4 v2 = __ldg((const float4*)(in + (size_t)j2 * HID) + lane);
        float4 v3 = __ldg((const float4*)(in + (size_t)j3 * HID) + lane);
        acc.x += (v0.x + v1.x) + (v2.x + v3.x);
        acc.y += (v0.y + v1.y) + (v2.y + v3.y);
        acc.z += (v0.z + v1.z) + (v2.z + v3.z);
        acc.w += (v0.w + v1.w) + (v2.w + v3.w);
    }
    for (; k < d; k++) {
        int j = g_col[s + k];
        float4 v = __ldg((const float4*)(in + (size_t)j * HID) + lane);
        acc.x += v.x; acc.y += v.y; acc.z += v.z; acc.w += v.w;
    }
    float inv = g_inv[node];
    acc.x *= inv; acc.y *= inv; acc.z *= inv; acc.w *= inv;
    bf16 h0, l0, h1, l1, h2, l2, h3, l3;
    split_bf(acc.x, h0, l0); split_bf(acc.y, h1, l1);
    split_bf(acc.z, h2, l2); split_bf(acc.w, h3, l3);
    size_t o = (size_t)node * HID + lane * 4;
    *(uint2*)(g_mhi + o) = make_uint2(pack_bf2(h0, h1), pack_bf2(h2, h3));
    *(uint2*)(g_mlo + o) = make_uint2(pack_bf2(l0, l1), pack_bf2(l2, l3));
}

// ---------------- mma.sync GEMM (bf16 tiles preconverted) --------------------
// out = mean @ Wl^T + h @ Wr^T + b (opt ReLU), C += Ahi*Bhi + Ahi*Blo + Alo*Bhi.
// CTA: 128x128 tile, 256 thr (8 warps, 4m x 2n), K=256 in 4 chunks of 64.
#define SM_AHI  0
#define SM_ALO  16384
#define SM_WHI  32768
#define SM_WLO  49152
#define SM_TOTAL 65536

__global__ void __launch_bounds__(256, 2) k_mma(
    const float* __restrict__ bias, float* __restrict__ out_ext,
    int src_sel, int widx, int dst_sel, int relu)
{
    extern __shared__ char smem[];
    const bf16* Ahi2 = (src_sel == 0) ? g_xhi : (src_sel == 1 ? g_h1hi : g_h2hi);
    const bf16* Alo2 = (src_sel == 0) ? g_xlo : (src_sel == 1 ? g_h1lo : g_h2lo);
    float* out = (dst_sel == 1) ? g_h1 : (dst_sel == 2 ? g_h2 : out_ext);
    bf16* ohi = (dst_sel == 1) ? g_h1hi : (dst_sel == 2 ? g_h2hi : (bf16*)0);
    bf16* olo = (dst_sel == 1) ? g_h1lo : (dst_sel == 2 ? g_h2lo : (bf16*)0);

    uint32_t sb = smem_u32(smem);
    int tid = threadIdx.x;
    int lane = tid & 31, warp = tid >> 5;
    int wm = warp & 3, wn = warp >> 2;      // 4m x 2n warp grid
    int row0 = blockIdx.x * TILE_M;

    float acc[2][8][4];
#pragma unroll
    for (int mt = 0; mt < 2; mt++)
#pragma unroll
        for (int nt = 0; nt < 8; nt++)
#pragma unroll
            for (int q = 0; q < 4; q++) acc[mt][nt][q] = 0.f;

    int l15 = lane & 15, lhi = lane >> 4;
    int bn = ((lane >> 4) << 3) + (lane & 7);
    int bk = ((lane >> 3) & 1) * 16;

    int fr = tid >> 1;            // fill row 0..127
    int fh = tid & 1;             // fill half (32-col / 64-byte granule)

    for (int kc = 0; kc < 4; kc++) {
        const bf16 *Ah, *Al, *Wh, *Wl;
        if (kc < 2) {
            Ah = g_mhi; Al = g_mlo;
            Wh = g_whi + (size_t)(2 * widx) * HID * HID;
            Wl = g_wlo + (size_t)(2 * widx) * HID * HID;
        } else {
            Ah = Ahi2;  Al = Alo2;
            Wh = g_whi + (size_t)(2 * widx + 1) * HID * HID;
            Wl = g_wlo + (size_t)(2 * widx + 1) * HID * HID;
        }
        int koff = (kc & 1) * 64;

        // ---- fill: 4 tiles x 16KB, pure 16B copies into swizzled smem ----
        {
            int grow = row0 + fr;
            bool ok = grow < NN;
            size_t abase = (size_t)grow * HID + koff + fh * 32;
            size_t wbase = (size_t)fr * HID + koff + fh * 32;
            const uint4 zero4 = make_uint4(0, 0, 0, 0);
#pragma unroll
            for (int i = 0; i < 4; i++) {
                uint32_t dof = SWZ((uint32_t)(fr * 128 + fh * 64 + i * 16));
                uint4 vah = ok ? *(const uint4*)(Ah + abase + i * 8) : zero4;
                uint4 val = ok ? *(const uint4*)(Al + abase + i * 8) : zero4;
                uint4 vwh = *(const uint4*)(Wh + wbase + i * 8);
                uint4 vwl = *(const uint4*)(Wl + wbase + i * 8);
                *(uint4*)(smem + SM_AHI + dof) = vah;
                *(uint4*)(smem + SM_ALO + dof) = val;
                *(uint4*)(smem + SM_WHI + dof) = vwh;
                *(uint4*)(smem + SM_WLO + dof) = vwl;
            }
        }
        __syncthreads();

        // ---- 4 x k16 mma steps ----
#pragma unroll
        for (int ks = 0; ks < 4; ks++) {
            int kb2 = ks * 32;
            uint32_t a_hi[2][4], a_lo[2][4];
#pragma unroll
            for (int mt = 0; mt < 2; mt++) {
                uint32_t so = SWZ((uint32_t)((wm * 32 + mt * 16 + l15) * 128 +
                                             kb2 + lhi * 16));
                ldsm4(a_hi[mt], sb + SM_AHI + so);
                ldsm4(a_lo[mt], sb + SM_ALO + so);
            }
#pragma unroll
            for (int g = 0; g < 4; g++) {
                uint32_t so = SWZ((uint32_t)((wn * 64 + g * 16 + bn) * 128 +
                                             kb2 + bk));
                uint32_t bh[4], bl[4];
                ldsm4(bh, sb + SM_WHI + so);
                ldsm4(bl, sb + SM_WLO + so);
#pragma unroll
                for (int mt = 0; mt < 2; mt++)
#pragma unroll
                    for (int sub = 0; sub < 2; sub++) {
                        float* c = acc[mt][g * 2 + sub];
                        mma_bf16(c, a_hi[mt], bh + sub * 2);
                        mma_bf16(c, a_hi[mt], bl + sub * 2);
                        mma_bf16(c, a_lo[mt], bh + sub * 2);
                    }
            }
        }
        __syncthreads();
    }

    // ---- epilogue: bias + opt relu; fp32 store (+ bf16 hi/lo for h dst) ----
#pragma unroll
    for (int nt = 0; nt < 8; nt++) {
        int col = wn * 64 + nt * 8 + (lane & 3) * 2;
        float bx = __ldg(bias + col);
        float by = __ldg(bias + col + 1);
#pragma unroll
        for (int mt = 0; mt < 2; mt++) {
            int rbase = row0 + wm * 32 + mt * 16 + (lane >> 2);
            float* c = acc[mt][nt];
#pragma unroll
            for (int half = 0; half < 2; half++) {
                int r = rbase + half * 8;
                if (r >= NN) continue;
                float2 o = make_float2(c[half * 2 + 0] + bx, c[half * 2 + 1] + by);
                if (relu) { o.x = fmaxf(o.x, 0.f); o.y = fmaxf(o.y, 0.f); }
                size_t off = (size_t)r * HID + col;
                *(float2*)(out + off) = o;
                if (ohi) {
                    bf16 hx, lx, hy, ly;
                    split_bf(o.x, hx, lx); split_bf(o.y, hy, ly);
                    *(uint32_t*)(ohi + off) = pack_bf2(hx, hy);
                    *(uint32_t*)(olo + off) = pack_bf2(lx, ly);
                }
            }
        }
    }
}

// ---------------- launch -----------------------------------------------------
extern "C" void kernel_launch(void* const* d_in, const int* in_sizes, int n_in,
                              void* d_out, int out_size) {
    const float* x   = (const float*)d_in[0];
    const void*  ei  = d_in[1];
    const float* Wl1 = (const float*)d_in[2];
    const float* Wr1 = (const float*)d_in[3];
    const float* b1  = (const float*)d_in[4];
    const float* Wl2 = (const float*)d_in[5];
    const float* Wr2 = (const float*)d_in[6];
    const float* b2  = (const float*)d_in[7];
    const float* Wl3 = (const float*)d_in[8];
    const float* Wr3 = (const float*)d_in[9];
    const float* b3  = (const float*)d_in[10];
    float* out = (float*)d_out;

    cudaFuncSetAttribute(k_mma, cudaFuncAttributeMaxDynamicSharedMemorySize,
                         SM_TOTAL);

    // CSR build + operand pre-conversion
    k_detect<<<1, 32>>>(ei);
    k_zero_deg<<<(NN + 255) / 256, 256>>>();
    k_count<<<(NE + 255) / 256, 256>>>(ei);
    int nb = (NN + 1023) / 1024;
    k_scan1<<<nb, 1024>>>();
    k_scan2<<<1, 32>>>(nb);
    k_scan3<<<(NN + 255) / 256, 256>>>();
    k_fill<<<(NE + 255) / 256, 256>>>(ei);
    k_wconv<<<(6 * HID * HID + 255) / 256, 256>>>(Wl1, Wr1, Wl2, Wr2, Wl3, Wr3);
    k_xconv<<<((NN * HID / 4) + 255) / 256, 256>>>(x);

    int ablocks = (NN + 7) / 8;

    // layer 1 (ReLU): agg(x) -> mean bf16; gemm -> h1 (fp32 + bf16)
    k_agg<<<ablocks, 256>>>(x, 0);
    k_mma<<<GBLK, 256, SM_TOTAL>>>(b1, out, 0, 0, 1, 1);
    // layer 2: agg(h1) -> mean; gemm -> h2 (fp32 + bf16)
    k_agg<<<ablocks, 256>>>(x, 1);
    k_mma<<<GBLK, 256, SM_TOTAL>>>(b2, out, 1, 1, 2, 0);
    // layer 3: agg(h2) -> mean; gemm -> d_out (fp32 only)
    k_agg<<<ablocks, 256>>>(x, 2);
    k_mma<<<GBLK, 256, SM_TOTAL>>>(b3, out, 2, 2, 3, 0);
}

// round 10
// speedup vs baseline: 2.2793x; 1.4086x over previous
#include <cuda_runtime.h>
#include <cuda_fp16.h>
#include <cstdint>

#define NN 50000
#define NE 600000
#define HID 128
#define TILE_M 128
#define GBLK ((NN + TILE_M - 1) / TILE_M)

// ---------------- scratch (static device globals; no allocations) ------------
__device__ int   g_deg[NN];
__device__ int   g_rowptr[NN];
__device__ int   g_cursor[NN];
__device__ float g_inv[NN];
__device__ int   g_col[NE];
__device__ int   g_bsums[64];
__device__ float g_h1[(size_t)NN * HID];
__device__ float g_h2[(size_t)NN * HID];
// fp16 operand buffers: A-side hi only; W-side hi+lo
__device__ __half g_mhi[(size_t)NN * HID];
__device__ __half g_xhi[(size_t)NN * HID];
__device__ __half g_h1hi[(size_t)NN * HID];
__device__ __half g_h2hi[(size_t)NN * HID];
__device__ __half g_whi[6 * HID * HID], g_wlo[6 * HID * HID];

// ---------------- helpers ----------------------------------------------------
__device__ __forceinline__ uint32_t smem_u32(const void* p) {
    uint32_t a;
    asm("{ .reg .u64 t; cvta.to.shared.u64 t, %1; cvt.u32.u64 %0, t; }"
        : "=r"(a) : "l"(p));
    return a;
}

#define SWZ(o) ((o) ^ (((o) >> 3) & 0x70))

__device__ __forceinline__ void ldsm4(uint32_t* r, uint32_t addr) {
    asm volatile("ldmatrix.sync.aligned.m8n8.x4.shared.b16 {%0,%1,%2,%3}, [%4];"
                 : "=r"(r[0]), "=r"(r[1]), "=r"(r[2]), "=r"(r[3]) : "r"(addr));
}

__device__ __forceinline__ void mma_f16(float* c, const uint32_t* a,
                                        const uint32_t* b) {
    asm volatile(
        "mma.sync.aligned.m16n8k16.row.col.f32.f16.f16.f32 "
        "{%0,%1,%2,%3}, {%4,%5,%6,%7}, {%8,%9}, {%0,%1,%2,%3};"
        : "+f"(c[0]), "+f"(c[1]), "+f"(c[2]), "+f"(c[3])
        : "r"(a[0]), "r"(a[1]), "r"(a[2]), "r"(a[3]), "r"(b[0]), "r"(b[1]));
}

__device__ __forceinline__ void cp16(uint32_t dst, const void* src, uint32_t n) {
    asm volatile("cp.async.cg.shared.global [%0], [%1], 16, %2;"
                 :: "r"(dst), "l"(src), "r"(n) : "memory");
}
__device__ __forceinline__ void cp_commit_wait() {
    asm volatile("cp.async.commit_group;" ::: "memory");
    asm volatile("cp.async.wait_group 0;" ::: "memory");
}

__device__ __forceinline__ uint32_t pack_h2(__half a, __half b) {
    __half2 t = __halves2half2(a, b);
    return *(uint32_t*)&t;
}

__device__ __forceinline__ void split_h(float v, __half& h, __half& l) {
    h = __float2half_rn(v);
    l = __float2half_rn(v - __half2float(h));
}

// int64-vs-int32 probe on first 64 src entries (block-uniform, <=512B reads)
__device__ __forceinline__ int probe64(const void* p) {
    const long long* q = (const long long*)p;
    for (int e = 0; e < 64; e++) {
        long long v = q[e];
        if (v < 0 || v >= NN) return 0;
    }
    return 1;
}

__device__ __forceinline__ int edge_val(const void* ei, int is64, int idx) {
    if (is64) return (int)((const long long*)ei)[idx];
    return ((const int*)ei)[idx];
}

// ---------------- CSR build --------------------------------------------------
__global__ void k_zero_deg() {
    int i = blockIdx.x * blockDim.x + threadIdx.x;
    if (i < NN) g_deg[i] = 0;
}

__global__ void k_count(const void* __restrict__ ei) {
    __shared__ int s64;
    if (threadIdx.x == 0) s64 = probe64(ei);
    __syncthreads();
    int e = blockIdx.x * blockDim.x + threadIdx.x;
    if (e < NE) {
        int d = edge_val(ei, s64, NE + e);
        if ((unsigned)d < NN) atomicAdd(&g_deg[d], 1);
    }
}

__global__ void k_scan1() {
    __shared__ int wsum[32];
    int i = blockIdx.x * 1024 + threadIdx.x;
    int lane = threadIdx.x & 31, w = threadIdx.x >> 5;
    int v = (i < NN) ? g_deg[i] : 0;
    int s = v;
#pragma unroll
    for (int o = 1; o < 32; o <<= 1) {
        int t = __shfl_up_sync(0xffffffffu, s, o);
        if (lane >= o) s += t;
    }
    if (lane == 31) wsum[w] = s;
    __syncthreads();
    if (w == 0) {
        int ws = wsum[lane];
#pragma unroll
        for (int o = 1; o < 32; o <<= 1) {
            int t = __shfl_up_sync(0xffffffffu, ws, o);
            if (lane >= o) ws += t;
        }
        wsum[lane] = ws;
    }
    __syncthreads();
    int incl = s + (w > 0 ? wsum[w - 1] : 0);
    if (i < NN) g_rowptr[i] = incl - v;
    if (threadIdx.x == 1023) g_bsums[blockIdx.x] = incl;
}

__global__ void k_scan2(int nb) {
    if (blockIdx.x == 0 && threadIdx.x == 0) {
        int acc = 0;
        for (int b = 0; b < nb; b++) { int t = g_bsums[b]; g_bsums[b] = acc; acc += t; }
    }
}

__global__ void k_scan3() {
    int i = blockIdx.x * blockDim.x + threadIdx.x;
    if (i < NN) {
        int rp = g_rowptr[i] + g_bsums[i >> 10];
        g_rowptr[i] = rp;
        g_cursor[i] = rp;
        int d = g_deg[i];
        g_inv[i] = 1.0f / (float)(d > 0 ? d : 1);
    }
}

__global__ void k_fill(const void* __restrict__ ei) {
    __shared__ int s64;
    if (threadIdx.x == 0) s64 = probe64(ei);
    __syncthreads();
    int e = blockIdx.x * blockDim.x + threadIdx.x;
    if (e < NE) {
        int s = edge_val(ei, s64, e);
        int d = edge_val(ei, s64, NE + e);
        if ((unsigned)s < NN && (unsigned)d < NN) {
            int pos = atomicAdd(&g_cursor[d], 1);
            if ((unsigned)pos < NE) g_col[pos] = s;
        }
    }
}

// ---------------- pre-convert: W -> fp16 hi/lo; x -> fp16 hi -----------------
__global__ void k_wconv(const float* __restrict__ w0, const float* __restrict__ w1,
                        const float* __restrict__ w2, const float* __restrict__ w3,
                        const float* __restrict__ w4, const float* __restrict__ w5) {
    int idx = blockIdx.x * blockDim.x + threadIdx.x;
    if (idx >= 6 * HID * HID) return;
    int m = idx >> 14, off = idx & 16383;
    const float* w = (m == 0) ? w0 : (m == 1) ? w1 : (m == 2) ? w2
                   : (m == 3) ? w3 : (m == 4) ? w4 : w5;
    __half h, l;
    split_h(w[off], h, l);
    g_whi[idx] = h; g_wlo[idx] = l;
}

__global__ void k_xconv(const float* __restrict__ x) {
    int idx = blockIdx.x * blockDim.x + threadIdx.x;   // per 4 elements
    if ((size_t)idx * 4 >= (size_t)NN * HID) return;
    float4 v = *(const float4*)(x + (size_t)idx * 4);
    *(uint2*)(g_xhi + (size_t)idx * 4) = make_uint2(
        pack_h2(__float2half_rn(v.x), __float2half_rn(v.y)),
        pack_h2(__float2half_rn(v.z), __float2half_rn(v.w)));
}

// ---------------- aggregation: warp per node, lane = float4, unroll 8 --------
__global__ void __launch_bounds__(256) k_agg(const float* __restrict__ x_ext,
                                             int src_sel) {
    const float* in = (src_sel == 0) ? x_ext : (src_sel == 1 ? g_h1 : g_h2);
    int node = blockIdx.x * 8 + (threadIdx.x >> 5);
    int lane = threadIdx.x & 31;
    if (node >= NN) return;
    int s = g_rowptr[node];
    int d = g_deg[node];
    float4 acc = make_float4(0.f, 0.f, 0.f, 0.f);
    int k = 0;
    for (; k + 8 <= d; k += 8) {
        float4 v[8];
#pragma unroll
        for (int u = 0; u < 8; u++) {
            int j = g_col[s + k + u];
            v[u] = __ldg((const float4*)(in + (size_t)j * HID) + lane);
        }
#pragma unroll
        for (int u = 0; u < 8; u++) {
            acc.x += v[u].x; acc.y += v[u].y;
            acc.z += v[u].z; acc.w += v[u].w;
        }
    }
    for (; k < d; k++) {
        int j = g_col[s + k];
        float4 v = __ldg((const float4*)(in + (size_t)j * HID) + lane);
        acc.x += v.x; acc.y += v.y; acc.z += v.z; acc.w += v.w;
    }
    float inv = g_inv[node];
    acc.x *= inv; acc.y *= inv; acc.z *= inv; acc.w *= inv;
    size_t o = (size_t)node * HID + lane * 4;
    *(uint2*)(g_mhi + o) = make_uint2(
        pack_h2(__float2half_rn(acc.x), __float2half_rn(acc.y)),
        pack_h2(__float2half_rn(acc.z), __float2half_rn(acc.w)));
}

// ---------------- mma.sync GEMM (fp16 2-term) --------------------------------
// out = mean @ Wl^T + h @ Wr^T + b (opt ReLU).
// C += Ahi*Whi + Ahi*Wlo  (fp16 split; dropped Alo*Whi ~ 2^-11).
// CTA: 128x128 tile, 256 thr (8 warps, 4m x 2n), K=256 in 4 chunks of 64.
#define SM_AHI  0
#define SM_WHI  16384
#define SM_WLO  32768
#define SM_TOTAL 49152

__global__ void __launch_bounds__(256, 2) k_mma(
    const float* __restrict__ bias, float* __restrict__ out_ext,
    int src_sel, int widx, int dst_sel, int relu)
{
    extern __shared__ char smem[];
    const __half* Ahx = (src_sel == 0) ? g_xhi : (src_sel == 1 ? g_h1hi : g_h2hi);
    float* out = (dst_sel == 1) ? g_h1 : (dst_sel == 2 ? g_h2 : out_ext);
    __half* ohi = (dst_sel == 1) ? g_h1hi : (dst_sel == 2 ? g_h2hi : (__half*)0);

    uint32_t sb = smem_u32(smem);
    int tid = threadIdx.x;
    int lane = tid & 31, warp = tid >> 5;
    int wm = warp & 3, wn = warp >> 2;      // 4m x 2n warp grid
    int row0 = blockIdx.x * TILE_M;

    float acc[2][8][4];
#pragma unroll
    for (int mt = 0; mt < 2; mt++)
#pragma unroll
        for (int nt = 0; nt < 8; nt++)
#pragma unroll
            for (int q = 0; q < 4; q++) acc[mt][nt][q] = 0.f;

    int l15 = lane & 15, lhi = lane >> 4;
    int bn = ((lane >> 4) << 3) + (lane & 7);
    int bk = ((lane >> 3) & 1) * 16;

    int fr = tid >> 1;            // fill row 0..127
    int fh = tid & 1;             // fill half (64-byte granule)

    for (int kc = 0; kc < 4; kc++) {
        const __half *Ah, *Wh, *Wl;
        if (kc < 2) {
            Ah = g_mhi;
            Wh = g_whi + (size_t)(2 * widx) * HID * HID;
            Wl = g_wlo + (size_t)(2 * widx) * HID * HID;
        } else {
            Ah = Ahx;
            Wh = g_whi + (size_t)(2 * widx + 1) * HID * HID;
            Wl = g_wlo + (size_t)(2 * widx + 1) * HID * HID;
        }
        int koff = (kc & 1) * 64;

        // ---- fill via cp.async: A-hi 16KB + W-hi 16KB + W-lo 16KB ----
        {
            int grow = row0 + fr;
            uint32_t aok = (grow < NN) ? 16u : 0u;
            size_t abase = (size_t)grow * HID + koff + fh * 32;
            size_t wbase = (size_t)fr * HID + koff + fh * 32;
#pragma unroll
            for (int i = 0; i < 4; i++) {
                uint32_t dof = SWZ((uint32_t)(fr * 128 + fh * 64 + i * 16));
                cp16(sb + SM_AHI + dof, Ah + abase + i * 8, aok);
                cp16(sb + SM_WHI + dof, Wh + wbase + i * 8, 16u);
                cp16(sb + SM_WLO + dof, Wl + wbase + i * 8, 16u);
            }
        }
        cp_commit_wait();
        __syncthreads();

        // ---- 4 x k16 mma steps ----
#pragma unroll
        for (int ks = 0; ks < 4; ks++) {
            int kb2 = ks * 32;
            uint32_t a_hi[2][4];
#pragma unroll
            for (int mt = 0; mt < 2; mt++) {
                uint32_t so = SWZ((uint32_t)((wm * 32 + mt * 16 + l15) * 128 +
                                             kb2 + lhi * 16));
                ldsm4(a_hi[mt], sb + SM_AHI + so);
            }
#pragma unroll
            for (int g = 0; g < 4; g++) {
                uint32_t so = SWZ((uint32_t)((wn * 64 + g * 16 + bn) * 128 +
                                             kb2 + bk));
                uint32_t bh[4], bl[4];
                ldsm4(bh, sb + SM_WHI + so);
                ldsm4(bl, sb + SM_WLO + so);
#pragma unroll
                for (int mt = 0; mt < 2; mt++)
#pragma unroll
                    for (int sub = 0; sub < 2; sub++) {
                        float* c = acc[mt][g * 2 + sub];
                        mma_f16(c, a_hi[mt], bh + sub * 2);
                        mma_f16(c, a_hi[mt], bl + sub * 2);
                    }
            }
        }
        __syncthreads();
    }

    // ---- epilogue: bias + opt relu; fp32 store (+ fp16 hi for h dst) ----
#pragma unroll
    for (int nt = 0; nt < 8; nt++) {
        int col = wn * 64 + nt * 8 + (lane & 3) * 2;
        float bx = __ldg(bias + col);
        float by = __ldg(bias + col + 1);
#pragma unroll
        for (int mt = 0; mt < 2; mt++) {
            int rbase = row0 + wm * 32 + mt * 16 + (lane >> 2);
            float* c = acc[mt][nt];
#pragma unroll
            for (int half_i = 0; half_i < 2; half_i++) {
                int r = rbase + half_i * 8;
                if (r >= NN) continue;
                float2 o = make_float2(c[half_i * 2 + 0] + bx,
                                       c[half_i * 2 + 1] + by);
                if (relu) { o.x = fmaxf(o.x, 0.f); o.y = fmaxf(o.y, 0.f); }
                size_t off = (size_t)r * HID + col;
                *(float2*)(out + off) = o;
                if (ohi)
                    *(uint32_t*)(ohi + off) =
                        pack_h2(__float2half_rn(o.x), __float2half_rn(o.y));
            }
        }
    }
}

// ---------------- launch -----------------------------------------------------
extern "C" void kernel_launch(void* const* d_in, const int* in_sizes, int n_in,
                              void* d_out, int out_size) {
    const float* x   = (const float*)d_in[0];
    const void*  ei  = d_in[1];
    const float* Wl1 = (const float*)d_in[2];
    const float* Wr1 = (const float*)d_in[3];
    const float* b1  = (const float*)d_in[4];
    const float* Wl2 = (const float*)d_in[5];
    const float* Wr2 = (const float*)d_in[6];
    const float* b2  = (const float*)d_in[7];
    const float* Wl3 = (const float*)d_in[8];
    const float* Wr3 = (const float*)d_in[9];
    const float* b3  = (const float*)d_in[10];
    float* out = (float*)d_out;

    cudaFuncSetAttribute(k_mma, cudaFuncAttributeMaxDynamicSharedMemorySize,
                         SM_TOTAL);

    // CSR build + operand pre-conversion
    k_zero_deg<<<(NN + 255) / 256, 256>>>();
    k_count<<<(NE + 255) / 256, 256>>>(ei);
    int nb = (NN + 1023) / 1024;
    k_scan1<<<nb, 1024>>>();
    k_scan2<<<1, 32>>>(nb);
    k_scan3<<<(NN + 255) / 256, 256>>>();
    k_fill<<<(NE + 255) / 256, 256>>>(ei);
    k_wconv<<<(6 * HID * HID + 255) / 256, 256>>>(Wl1, Wr1, Wl2, Wr2, Wl3, Wr3);
    k_xconv<<<((NN * HID / 4) + 255) / 256, 256>>>(x);

    int ablocks = (NN + 7) / 8;

    // layer 1 (ReLU): agg(x) -> mean fp16; gemm -> h1 (fp32 + fp16)
    k_agg<<<ablocks, 256>>>(x, 0);
    k_mma<<<GBLK, 256, SM_TOTAL>>>(b1, out, 0, 0, 1, 1);
    // layer 2
    k_agg<<<ablocks, 256>>>(x, 1);
    k_mma<<<GBLK, 256, SM_TOTAL>>>(b2, out, 1, 1, 2, 0);
    // layer 3 -> d_out
    k_agg<<<ablocks, 256>>>(x, 2);
    k_mma<<<GBLK, 256, SM_TOTAL>>>(b3, out, 2, 2, 3, 0);
}

// round 12
// speedup vs baseline: 2.6920x; 1.1811x over previous
#include <cuda_runtime.h>
#include <cuda_fp16.h>
#include <cstdint>

#define NN 50000
#define NE 600000
#define HID 128
#define TILE_M 128
#define GBLK ((NN + TILE_M - 1) / TILE_M)

// ---------------- scratch (static device globals; no allocations) ------------
__device__ int   g_deg[NN];
__device__ int   g_rowptr[NN];
__device__ int   g_cursor[NN];
__device__ float g_inv[NN];
__device__ int   g_col[NE];
__device__ int   g_bsums[64];
// fp16 operand buffers: A-side hi only; W-side hi+lo. h lives as fp16 ONLY.
__device__ __half g_mhi[(size_t)NN * HID];
__device__ __half g_xhi[(size_t)NN * HID];
__device__ __half g_h1hi[(size_t)NN * HID];
__device__ __half g_h2hi[(size_t)NN * HID];
__device__ __half g_whi[6 * HID * HID], g_wlo[6 * HID * HID];

// ---------------- helpers ----------------------------------------------------
__device__ __forceinline__ uint32_t smem_u32(const void* p) {
    uint32_t a;
    asm("{ .reg .u64 t; cvta.to.shared.u64 t, %1; cvt.u32.u64 %0, t; }"
        : "=r"(a) : "l"(p));
    return a;
}

#define SWZ(o) ((o) ^ (((o) >> 3) & 0x70))

__device__ __forceinline__ void ldsm4(uint32_t* r, uint32_t addr) {
    asm volatile("ldmatrix.sync.aligned.m8n8.x4.shared.b16 {%0,%1,%2,%3}, [%4];"
                 : "=r"(r[0]), "=r"(r[1]), "=r"(r[2]), "=r"(r[3]) : "r"(addr));
}

__device__ __forceinline__ void mma_f16(float* c, const uint32_t* a,
                                        const uint32_t* b) {
    asm volatile(
        "mma.sync.aligned.m16n8k16.row.col.f32.f16.f16.f32 "
        "{%0,%1,%2,%3}, {%4,%5,%6,%7}, {%8,%9}, {%0,%1,%2,%3};"
        : "+f"(c[0]), "+f"(c[1]), "+f"(c[2]), "+f"(c[3])
        : "r"(a[0]), "r"(a[1]), "r"(a[2]), "r"(a[3]), "r"(b[0]), "r"(b[1]));
}

__device__ __forceinline__ void cp16(uint32_t dst, const void* src, uint32_t n) {
    asm volatile("cp.async.cg.shared.global [%0], [%1], 16, %2;"
                 :: "r"(dst), "l"(src), "r"(n) : "memory");
}
__device__ __forceinline__ void cp_commit_wait() {
    asm volatile("cp.async.commit_group;" ::: "memory");
    asm volatile("cp.async.wait_group 0;" ::: "memory");
}

__device__ __forceinline__ uint32_t pack_h2(__half a, __half b) {
    __half2 t = __halves2half2(a, b);
    return *(uint32_t*)&t;
}

__device__ __forceinline__ void split_h(float v, __half& h, __half& l) {
    h = __float2half_rn(v);
    l = __float2half_rn(v - __half2float(h));
}

// int64-vs-int32 probe on first 64 src entries (block-uniform, <=512B reads)
__device__ __forceinline__ int probe64(const void* p) {
    const long long* q = (const long long*)p;
    for (int e = 0; e < 64; e++) {
        long long v = q[e];
        if (v < 0 || v >= NN) return 0;
    }
    return 1;
}

__device__ __forceinline__ int edge_val(const void* ei, int is64, int idx) {
    if (is64) return (int)((const long long*)ei)[idx];
    return ((const int*)ei)[idx];
}

// ---------------- CSR build --------------------------------------------------
__global__ void k_zero_deg() {
    int i = blockIdx.x * blockDim.x + threadIdx.x;
    if (i < NN) g_deg[i] = 0;
}

__global__ void k_count(const void* __restrict__ ei) {
    __shared__ int s64;
    if (threadIdx.x == 0) s64 = probe64(ei);
    __syncthreads();
    int e = blockIdx.x * blockDim.x + threadIdx.x;
    if (e < NE) {
        int d = edge_val(ei, s64, NE + e);
        if ((unsigned)d < NN) atomicAdd(&g_deg[d], 1);
    }
}

__global__ void k_scan1() {
    __shared__ int wsum[32];
    int i = blockIdx.x * 1024 + threadIdx.x;
    int lane = threadIdx.x & 31, w = threadIdx.x >> 5;
    int v = (i < NN) ? g_deg[i] : 0;
    int s = v;
#pragma unroll
    for (int o = 1; o < 32; o <<= 1) {
        int t = __shfl_up_sync(0xffffffffu, s, o);
        if (lane >= o) s += t;
    }
    if (lane == 31) wsum[w] = s;
    __syncthreads();
    if (w == 0) {
        int ws = wsum[lane];
#pragma unroll
        for (int o = 1; o < 32; o <<= 1) {
            int t = __shfl_up_sync(0xffffffffu, ws, o);
            if (lane >= o) ws += t;
        }
        wsum[lane] = ws;
    }
    __syncthreads();
    int incl = s + (w > 0 ? wsum[w - 1] : 0);
    if (i < NN) g_rowptr[i] = incl - v;
    if (threadIdx.x == 1023) g_bsums[blockIdx.x] = incl;
}

// 64-wide Hillis-Steele over the (<=64) block sums -> exclusive
__global__ void k_scan2(int nb) {
    __shared__ int sh[64];
    int t = threadIdx.x;
    int v = (t < nb) ? g_bsums[t] : 0;
    sh[t] = v;
    __syncthreads();
#pragma unroll
    for (int o = 1; o < 64; o <<= 1) {
        int u = (t >= o) ? sh[t - o] : 0;
        __syncthreads();
        sh[t] += u;
        __syncthreads();
    }
    if (t < nb) g_bsums[t] = sh[t] - v;
}

__global__ void k_scan3() {
    int i = blockIdx.x * blockDim.x + threadIdx.x;
    if (i < NN) {
        int rp = g_rowptr[i] + g_bsums[i >> 10];
        g_rowptr[i] = rp;
        g_cursor[i] = rp;
        int d = g_deg[i];
        g_inv[i] = 1.0f / (float)(d > 0 ? d : 1);
    }
}

__global__ void k_fill(const void* __restrict__ ei) {
    __shared__ int s64;
    if (threadIdx.x == 0) s64 = probe64(ei);
    __syncthreads();
    int e = blockIdx.x * blockDim.x + threadIdx.x;
    if (e < NE) {
        int s = edge_val(ei, s64, e);
        int d = edge_val(ei, s64, NE + e);
        if ((unsigned)s < NN && (unsigned)d < NN) {
            int pos = atomicAdd(&g_cursor[d], 1);
            if ((unsigned)pos < NE) g_col[pos] = s;
        }
    }
}

// ---------------- pre-convert: W -> fp16 hi/lo; x -> fp16 hi -----------------
__global__ void k_wconv(const float* __restrict__ w0, const float* __restrict__ w1,
                        const float* __restrict__ w2, const float* __restrict__ w3,
                        const float* __restrict__ w4, const float* __restrict__ w5) {
    int idx = blockIdx.x * blockDim.x + threadIdx.x;
    if (idx >= 6 * HID * HID) return;
    int m = idx >> 14, off = idx & 16383;
    const float* w = (m == 0) ? w0 : (m == 1) ? w1 : (m == 2) ? w2
                   : (m == 3) ? w3 : (m == 4) ? w4 : w5;
    __half h, l;
    split_h(w[off], h, l);
    g_whi[idx] = h; g_wlo[idx] = l;
}

__global__ void k_xconv(const float* __restrict__ x) {
    int idx = blockIdx.x * blockDim.x + threadIdx.x;   // per 4 elements
    if ((size_t)idx * 4 >= (size_t)NN * HID) return;
    float4 v = *(const float4*)(x + (size_t)idx * 4);
    *(uint2*)(g_xhi + (size_t)idx * 4) = make_uint2(
        pack_h2(__float2half_rn(v.x), __float2half_rn(v.y)),
        pack_h2(__float2half_rn(v.z), __float2half_rn(v.w)));
}

// ---------------- aggregation: fp16 gather, fp32 accumulate ------------------
// warp per node, lane = 4 features (uint2 = 4 halves), unroll 8.
__global__ void __launch_bounds__(256) k_agg(int src_sel) {
    const __half* in = (src_sel == 0) ? g_xhi : (src_sel == 1 ? g_h1hi : g_h2hi);
    int node = blockIdx.x * 8 + (threadIdx.x >> 5);
    int lane = threadIdx.x & 31;
    if (node >= NN) return;
    int s = g_rowptr[node];
    int d = g_deg[node];
    float4 acc = make_float4(0.f, 0.f, 0.f, 0.f);
    int k = 0;
    for (; k + 8 <= d; k += 8) {
        uint2 v[8];
#pragma unroll
        for (int u = 0; u < 8; u++) {
            int j = g_col[s + k + u];
            v[u] = __ldg((const uint2*)(in + (size_t)j * HID) + lane);
        }
#pragma unroll
        for (int u = 0; u < 8; u++) {
            float2 a = __half22float2(*(__half2*)&v[u].x);
            float2 b = __half22float2(*(__half2*)&v[u].y);
            acc.x += a.x; acc.y += a.y; acc.z += b.x; acc.w += b.y;
        }
    }
    for (; k < d; k++) {
        int j = g_col[s + k];
        uint2 v = __ldg((const uint2*)(in + (size_t)j * HID) + lane);
        float2 a = __half22float2(*(__half2*)&v.x);
        float2 b = __half22float2(*(__half2*)&v.y);
        acc.x += a.x; acc.y += a.y; acc.z += b.x; acc.w += b.y;
    }
    float inv = g_inv[node];
    acc.x *= inv; acc.y *= inv; acc.z *= inv; acc.w *= inv;
    size_t o = (size_t)node * HID + lane * 4;
    *(uint2*)(g_mhi + o) = make_uint2(
        pack_h2(__float2half_rn(acc.x), __float2half_rn(acc.y)),
        pack_h2(__float2half_rn(acc.z), __float2half_rn(acc.w)));
}

// ---------------- mma.sync GEMM (fp16 2-term) --------------------------------
// out = mean @ Wl^T + h @ Wr^T + b (opt ReLU).
// C += Ahi*Whi + Ahi*Wlo  (fp16 split; dropped Alo*Whi ~ 2^-11).
// CTA: 128x128 tile, 256 thr (8 warps, 4m x 2n), K=256 in 4 chunks of 64.
#define SM_AHI  0
#define SM_WHI  16384
#define SM_WLO  32768
#define SM_TOTAL 49152

__global__ void __launch_bounds__(256, 2) k_mma(
    const float* __restrict__ bias, float* __restrict__ out_ext,
    int src_sel, int widx, int dst_sel, int relu)
{
    extern __shared__ char smem[];
    const __half* Ahx = (src_sel == 0) ? g_xhi : (src_sel == 1 ? g_h1hi : g_h2hi);
    __half* ohi = (dst_sel == 1) ? g_h1hi : (dst_sel == 2 ? g_h2hi : (__half*)0);

    uint32_t sb = smem_u32(smem);
    int tid = threadIdx.x;
    int lane = tid & 31, warp = tid >> 5;
    int wm = warp & 3, wn = warp >> 2;      // 4m x 2n warp grid
    int row0 = blockIdx.x * TILE_M;

    float acc[2][8][4];
#pragma unroll
    for (int mt = 0; mt < 2; mt++)
#pragma unroll
        for (int nt = 0; nt < 8; nt++)
#pragma unroll
            for (int q = 0; q < 4; q++) acc[mt][nt][q] = 0.f;

    int l15 = lane & 15, lhi = lane >> 4;
    int bn = ((lane >> 4) << 3) + (lane & 7);
    int bk = ((lane >> 3) & 1) * 16;

    int fr = tid >> 1;            // fill row 0..127
    int fh = tid & 1;             // fill half (64-byte granule)

    for (int kc = 0; kc < 4; kc++) {
        const __half *Ah, *Wh, *Wl;
        if (kc < 2) {
            Ah = g_mhi;
            Wh = g_whi + (size_t)(2 * widx) * HID * HID;
            Wl = g_wlo + (size_t)(2 * widx) * HID * HID;
        } else {
            Ah = Ahx;
            Wh = g_whi + (size_t)(2 * widx + 1) * HID * HID;
            Wl = g_wlo + (size_t)(2 * widx + 1) * HID * HID;
        }
        int koff = (kc & 1) * 64;

        // ---- fill via cp.async: A-hi 16KB + W-hi 16KB + W-lo 16KB ----
        {
            int grow = row0 + fr;
            uint32_t aok = (grow < NN) ? 16u : 0u;
            size_t abase = (size_t)grow * HID + koff + fh * 32;
            size_t wbase = (size_t)fr * HID + koff + fh * 32;
#pragma unroll
            for (int i = 0; i < 4; i++) {
                uint32_t dof = SWZ((uint32_t)(fr * 128 + fh * 64 + i * 16));
                cp16(sb + SM_AHI + dof, Ah + abase + i * 8, aok);
                cp16(sb + SM_WHI + dof, Wh + wbase + i * 8, 16u);
                cp16(sb + SM_WLO + dof, Wl + wbase + i * 8, 16u);
            }
        }
        cp_commit_wait();
        __syncthreads();

        // ---- 4 x k16 mma steps ----
#pragma unroll
        for (int ks = 0; ks < 4; ks++) {
            int kb2 = ks * 32;
            uint32_t a_hi[2][4];
#pragma unroll
            for (int mt = 0; mt < 2; mt++) {
                uint32_t so = SWZ((uint32_t)((wm * 32 + mt * 16 + l15) * 128 +
                                             kb2 + lhi * 16));
                ldsm4(a_hi[mt], sb + SM_AHI + so);
            }
#pragma unroll
            for (int g = 0; g < 4; g++) {
                uint32_t so = SWZ((uint32_t)((wn * 64 + g * 16 + bn) * 128 +
                                             kb2 + bk));
                uint32_t bh[4], bl[4];
                ldsm4(bh, sb + SM_WHI + so);
                ldsm4(bl, sb + SM_WLO + so);
#pragma unroll
                for (int mt = 0; mt < 2; mt++)
#pragma unroll
                    for (int sub = 0; sub < 2; sub++) {
                        float* c = acc[mt][g * 2 + sub];
                        mma_f16(c, a_hi[mt], bh + sub * 2);
                        mma_f16(c, a_hi[mt], bl + sub * 2);
                    }
            }
        }
        __syncthreads();
    }

    // ---- epilogue: bias + opt relu; fp16 store for h, fp32 for final --------
#pragma unroll
    for (int nt = 0; nt < 8; nt++) {
        int col = wn * 64 + nt * 8 + (lane & 3) * 2;
        float bx = __ldg(bias + col);
        float by = __ldg(bias + col + 1);
#pragma unroll
        for (int mt = 0; mt < 2; mt++) {
            int rbase = row0 + wm * 32 + mt * 16 + (lane >> 2);
            float* c = acc[mt][nt];
#pragma unroll
            for (int half_i = 0; half_i < 2; half_i++) {
                int r = rbase + half_i * 8;
                if (r >= NN) continue;
                float2 o = make_float2(c[half_i * 2 + 0] + bx,
                                       c[half_i * 2 + 1] + by);
                if (relu) { o.x = fmaxf(o.x, 0.f); o.y = fmaxf(o.y, 0.f); }
                size_t off = (size_t)r * HID + col;
                if (ohi)
                    *(uint32_t*)(ohi + off) =
                        pack_h2(__float2half_rn(o.x), __float2half_rn(o.y));
                else
                    *(float2*)(out_ext + off) = o;
            }
        }
    }
}

// ---------------- launch -----------------------------------------------------
extern "C" void kernel_launch(void* const* d_in, const int* in_sizes, int n_in,
                              void* d_out, int out_size) {
    const float* x   = (const float*)d_in[0];
    const void*  ei  = d_in[1];
    const float* Wl1 = (const float*)d_in[2];
    const float* Wr1 = (const float*)d_in[3];
    const float* b1  = (const float*)d_in[4];
    const float* Wl2 = (const float*)d_in[5];
    const float* Wr2 = (const float*)d_in[6];
    const float* b2  = (const float*)d_in[7];
    const float* Wl3 = (const float*)d_in[8];
    const float* Wr3 = (const float*)d_in[9];
    const float* b3  = (const float*)d_in[10];
    float* out = (float*)d_out;

    cudaFuncSetAttribute(k_mma, cudaFuncAttributeMaxDynamicSharedMemorySize,
                         SM_TOTAL);

    // CSR build + operand pre-conversion
    k_zero_deg<<<(NN + 255) / 256, 256>>>();
    k_count<<<(NE + 255) / 256, 256>>>(ei);
    int nb = (NN + 1023) / 1024;
    k_scan1<<<nb, 1024>>>();
    k_scan2<<<1, 64>>>(nb);
    k_scan3<<<(NN + 255) / 256, 256>>>();
    k_fill<<<(NE + 255) / 256, 256>>>(ei);
    k_wconv<<<(6 * HID * HID + 255) / 256, 256>>>(Wl1, Wr1, Wl2, Wr2, Wl3, Wr3);
    k_xconv<<<((NN * HID / 4) + 255) / 256, 256>>>(x);

    int ablocks = (NN + 7) / 8;

    // layer 1 (ReLU): agg(x fp16) -> mean fp16; gemm -> h1 fp16
    k_agg<<<ablocks, 256>>>(0);
    k_mma<<<GBLK, 256, SM_TOTAL>>>(b1, out, 0, 0, 1, 1);
    // layer 2
    k_agg<<<ablocks, 256>>>(1);
    k_mma<<<GBLK, 256, SM_TOTAL>>>(b2, out, 1, 1, 2, 0);
    // layer 3 -> d_out (fp32)
    k_agg<<<ablocks, 256>>>(2);
    k_mma<<<GBLK, 256, SM_TOTAL>>>(b3, out, 2, 2, 3, 0);
}